// round 16
// baseline (speedup 1.0000x reference)
#include <cuda_runtime.h>
#include <cstddef>
#include <cstdint>

// FINAL (converged) — source-indexed scatter-on-store, DRAM-roofline-pinned.
// 10.72us modal over 5 runs (band 10.72-10.98) = 95.5% of 8 TB/s HBM spec on
// irreducible 81.9 MB traffic (input read exactly once by 4x4-pool partition;
// output 6%). Adjudicated levers (R3-R15): sequential-load/scatter-store WIN
// (+2.4%); .L2::256B hint stabilizes at band bottom; L2 persist policy
// unavailable (carveout = forbidden device limit); larger per-thread tiles
// -19% (occupancy collapse); 1D grid / __ldg neutral. DRAM is the sole
// binding pipe (fma/alu ~4.5%, issue ~12%, occ ~83% all slack).
//
//   thread handles source rows 4*sr..4*sr+3, source cols 8*t..8*t+7
//   -> two output pixels at out[bc,(sr+dy)%56,(2t+k+dx)%56], k=0,1
//   dy = W_shifts[b] (row shift), dx = H_shifts[b] (col shift), per reference.
// Loads: 4x 256-bit, perfectly sequential/sector-aligned per warp, .L2::256B
// fill-granule hint (warp consumes whole 256B spans — zero overfetch).
// Stores: 4B streaming (evict-first), carrying the modular wrap.
// Grid (7,384) x block (28,8): 18816 warps, MLP=4/thread, ~2 waves @ occ 83%.

#define H_IN 224
#define W_IN 224
#define H_OUT 56
#define W_OUT 56
#define CH 3

struct F8 { float v[8]; };

__device__ __forceinline__ F8 ldg256(const float* p) {
    F8 r;
    unsigned u0, u1, u2, u3, u4, u5, u6, u7;
    asm volatile("ld.global.nc.L2::256B.v8.b32 {%0,%1,%2,%3,%4,%5,%6,%7}, [%8];"
                 : "=r"(u0), "=r"(u1), "=r"(u2), "=r"(u3),
                   "=r"(u4), "=r"(u5), "=r"(u6), "=r"(u7)
                 : "l"(p));
    r.v[0] = __uint_as_float(u0); r.v[1] = __uint_as_float(u1);
    r.v[2] = __uint_as_float(u2); r.v[3] = __uint_as_float(u3);
    r.v[4] = __uint_as_float(u4); r.v[5] = __uint_as_float(u5);
    r.v[6] = __uint_as_float(u6); r.v[7] = __uint_as_float(u7);
    return r;
}

__device__ __forceinline__ void stg_stream(float* p, float v) {
    asm volatile("st.global.cs.f32 [%0], %1;" :: "l"(p), "f"(v) : "memory");
}

__global__ void __launch_bounds__(224)
downsample_wrap_translate_kernel(const float* __restrict__ img,
                                 const int* __restrict__ h_shifts,
                                 const int* __restrict__ w_shifts,
                                 float* __restrict__ out)
{
    // block (28,8); grid (7, B*C)
    const int t  = threadIdx.x;                       // source col pair 0..27
    const int sr = blockIdx.x * 8 + threadIdx.y;      // source out-row 0..55
    const int bc = blockIdx.y;                        // b*3 + c
    const int b  = bc / CH;

    const int dx = h_shifts[b];   // column shift
    const int dy = w_shifts[b];   // row shift

    // perfectly sequential loads: 4 input rows x 32 bytes
    const float* p = img + (size_t)bc * (H_IN * W_IN)
                         + (size_t)(sr * 4) * W_IN + t * 8;

    const F8 r0 = ldg256(p + 0 * W_IN);
    const F8 r1 = ldg256(p + 1 * W_IN);
    const F8 r2 = ldg256(p + 2 * W_IN);
    const F8 r3 = ldg256(p + 3 * W_IN);

    float s0 = (r0.v[0] + r0.v[1]) + (r0.v[2] + r0.v[3])
             + (r1.v[0] + r1.v[1]) + (r1.v[2] + r1.v[3])
             + (r2.v[0] + r2.v[1]) + (r2.v[2] + r2.v[3])
             + (r3.v[0] + r3.v[1]) + (r3.v[2] + r3.v[3]);
    float s1 = (r0.v[4] + r0.v[5]) + (r0.v[6] + r0.v[7])
             + (r1.v[4] + r1.v[5]) + (r1.v[6] + r1.v[7])
             + (r2.v[4] + r2.v[5]) + (r2.v[6] + r2.v[7])
             + (r3.v[4] + r3.v[5]) + (r3.v[6] + r3.v[7]);

    // scatter store with modular wrap
    int da = sr + dy; if (da >= H_OUT) da -= H_OUT;     // dest row
    int j0 = 2 * t + dx; if (j0 >= W_OUT) j0 -= W_OUT;  // dest col 0
    int j1 = j0 + 1;     if (j1 >= W_OUT) j1 -= W_OUT;  // dest col 1

    float* o = out + (size_t)bc * (H_OUT * W_OUT) + da * W_OUT;
    stg_stream(o + j0, s0 * (1.0f / 16.0f));
    stg_stream(o + j1, s1 * (1.0f / 16.0f));
}

extern "C" void kernel_launch(void* const* d_in, const int* in_sizes, int n_in,
                              void* d_out, int out_size)
{
    const float* img = (const float*)d_in[0];          // images (B,3,224,224) f32
    const int* h_shifts = (const int*)d_in[1];         // H_shifts (B,) i32 -> col shift
    const int* w_shifts = (const int*)d_in[2];         // W_shifts (B,) i32 -> row shift
    float* out = (float*)d_out;

    const int B = in_sizes[1];                         // 128
    dim3 block(28, 8);                                 // 224 threads
    dim3 grid(H_OUT / 8, B * CH);                      // (7, 384)
    downsample_wrap_translate_kernel<<<grid, block>>>(img, h_shifts, w_shifts, out);
}

// round 17
// speedup vs baseline: 1.0363x; 1.0363x over previous
#include <cuda_runtime.h>
#include <cstddef>
#include <cstdint>

// FINAL (converged) — source-indexed scatter-on-store, DRAM-roofline-pinned.
// Modal 10.72us over 6 runs (band 10.72-10.98) = 95.5% of 8 TB/s HBM spec on
// irreducible 81.9 MB traffic (input read exactly once by 4x4-pool partition;
// output 6%). Adjudicated levers (R3-R16): sequential-load/scatter-store WIN
// (+2.4%); .L2::256B hint stabilizes at band bottom; L2 persist policy
// unavailable (carveout = forbidden device limit); larger per-thread tiles
// -19% (occupancy collapse); 1D grid / __ldg neutral. DRAM is the sole
// binding pipe (fma/alu ~4.5%, issue ~12%, occ ~83-92% all slack).
//
//   thread handles source rows 4*sr..4*sr+3, source cols 8*t..8*t+7
//   -> two output pixels at out[bc,(sr+dy)%56,(2t+k+dx)%56], k=0,1
//   dy = W_shifts[b] (row shift), dx = H_shifts[b] (col shift), per reference.
// Loads: 4x 256-bit, perfectly sequential/sector-aligned per warp, .L2::256B
// fill-granule hint (warp consumes whole 256B spans — zero overfetch).
// Stores: 4B streaming (evict-first), carrying the modular wrap.
// Grid (7,384) x block (28,8): 18816 warps, MLP=4/thread, ~2 waves.

#define H_IN 224
#define W_IN 224
#define H_OUT 56
#define W_OUT 56
#define CH 3

struct F8 { float v[8]; };

__device__ __forceinline__ F8 ldg256(const float* p) {
    F8 r;
    unsigned u0, u1, u2, u3, u4, u5, u6, u7;
    asm volatile("ld.global.nc.L2::256B.v8.b32 {%0,%1,%2,%3,%4,%5,%6,%7}, [%8];"
                 : "=r"(u0), "=r"(u1), "=r"(u2), "=r"(u3),
                   "=r"(u4), "=r"(u5), "=r"(u6), "=r"(u7)
                 : "l"(p));
    r.v[0] = __uint_as_float(u0); r.v[1] = __uint_as_float(u1);
    r.v[2] = __uint_as_float(u2); r.v[3] = __uint_as_float(u3);
    r.v[4] = __uint_as_float(u4); r.v[5] = __uint_as_float(u5);
    r.v[6] = __uint_as_float(u6); r.v[7] = __uint_as_float(u7);
    return r;
}

__device__ __forceinline__ void stg_stream(float* p, float v) {
    asm volatile("st.global.cs.f32 [%0], %1;" :: "l"(p), "f"(v) : "memory");
}

__global__ void __launch_bounds__(224)
downsample_wrap_translate_kernel(const float* __restrict__ img,
                                 const int* __restrict__ h_shifts,
                                 const int* __restrict__ w_shifts,
                                 float* __restrict__ out)
{
    // block (28,8); grid (7, B*C)
    const int t  = threadIdx.x;                       // source col pair 0..27
    const int sr = blockIdx.x * 8 + threadIdx.y;      // source out-row 0..55
    const int bc = blockIdx.y;                        // b*3 + c
    const int b  = bc / CH;

    const int dx = h_shifts[b];   // column shift
    const int dy = w_shifts[b];   // row shift

    // perfectly sequential loads: 4 input rows x 32 bytes
    const float* p = img + (size_t)bc * (H_IN * W_IN)
                         + (size_t)(sr * 4) * W_IN + t * 8;

    const F8 r0 = ldg256(p + 0 * W_IN);
    const F8 r1 = ldg256(p + 1 * W_IN);
    const F8 r2 = ldg256(p + 2 * W_IN);
    const F8 r3 = ldg256(p + 3 * W_IN);

    float s0 = (r0.v[0] + r0.v[1]) + (r0.v[2] + r0.v[3])
             + (r1.v[0] + r1.v[1]) + (r1.v[2] + r1.v[3])
             + (r2.v[0] + r2.v[1]) + (r2.v[2] + r2.v[3])
             + (r3.v[0] + r3.v[1]) + (r3.v[2] + r3.v[3]);
    float s1 = (r0.v[4] + r0.v[5]) + (r0.v[6] + r0.v[7])
             + (r1.v[4] + r1.v[5]) + (r1.v[6] + r1.v[7])
             + (r2.v[4] + r2.v[5]) + (r2.v[6] + r2.v[7])
             + (r3.v[4] + r3.v[5]) + (r3.v[6] + r3.v[7]);

    // scatter store with modular wrap
    int da = sr + dy; if (da >= H_OUT) da -= H_OUT;     // dest row
    int j0 = 2 * t + dx; if (j0 >= W_OUT) j0 -= W_OUT;  // dest col 0
    int j1 = j0 + 1;     if (j1 >= W_OUT) j1 -= W_OUT;  // dest col 1

    float* o = out + (size_t)bc * (H_OUT * W_OUT) + da * W_OUT;
    stg_stream(o + j0, s0 * (1.0f / 16.0f));
    stg_stream(o + j1, s1 * (1.0f / 16.0f));
}

extern "C" void kernel_launch(void* const* d_in, const int* in_sizes, int n_in,
                              void* d_out, int out_size)
{
    const float* img = (const float*)d_in[0];          // images (B,3,224,224) f32
    const int* h_shifts = (const int*)d_in[1];         // H_shifts (B,) i32 -> col shift
    const int* w_shifts = (const int*)d_in[2];         // W_shifts (B,) i32 -> row shift
    float* out = (float*)d_out;

    const int B = in_sizes[1];                         // 128
    dim3 block(28, 8);                                 // 224 threads
    dim3 grid(H_OUT / 8, B * CH);                      // (7, 384)
    downsample_wrap_translate_kernel<<<grid, block>>>(img, h_shifts, w_shifts, out);
}